// round 3
// baseline (speedup 1.0000x reference)
#include <cuda_runtime.h>

// x[64, 64, 64, 128] fp32.
//   out1 = FWHT over axis 1 (i), out2 = FWHT over axis 2 (j) of out1.
// d_out = [out1 | out2].
//
// Fused single pass: each CTA owns the full (i=64, j=64) plane for one batch b
// and a 4-channel chunk, staged in smem (66.5 KB -> 3 CTAs/SM). Both FWHTs run
// register-resident; out1/out2 are stored straight from registers.
// Traffic: 128 MB read + 256 MB written = 384 MB (vs 512 MB for two-kernel).

#define DIM_C 128
#define ROWF 260                         // 64*4 + 4; 260 % 32 == 4 -> conflict-free
#define SMEM_BYTES (64 * ROWF * 4)       // 66,560 B

__global__ __launch_bounds__(256, 3)
void wht2_fused(const float* __restrict__ x,
                float* __restrict__ out1,
                float* __restrict__ out2)
{
    extern __shared__ float sm[];

    const int t  = threadIdx.x;
    const int b  = blockIdx.x >> 5;          // 64 batches
    const int cc = blockIdx.x & 31;          // 32 chunks of 4 channels
    // siblings (cc even/odd) cover the two 16B halves of each 32B sector
    const size_t base = (size_t)b * (64 * 64 * DIM_C) + cc * 4;

    // ---------- stage-in: float4 per (i,j), j fastest ----------
#pragma unroll
    for (int r = 0; r < 16; r++) {
        int lin = r * 256 + t;               // 0..4095 over (i,j)
        int j   = lin & 63;
        int i   = lin >> 6;
        float4 val = *reinterpret_cast<const float4*>(
            x + base + (size_t)i * 8192 + j * DIM_C);
        *reinterpret_cast<float4*>(sm + i * ROWF + j * 4) = val;
    }
    __syncthreads();

    float v[64];

    // ---------- phase A: FWHT over i; write smem + out1 from regs ----------
    {
        const int col = t;                   // j*4 + c  (j = t>>2, c = t&3)
        const int j   = t >> 2;
        const int c   = t & 3;
#pragma unroll
        for (int i = 0; i < 64; i++) v[i] = sm[i * ROWF + col];

#pragma unroll
        for (int h = 1; h < 64; h <<= 1)
#pragma unroll
            for (int s = 0; s < 64; s += 2 * h)
#pragma unroll
                for (int k = 0; k < h; k++) {
                    float a = v[s + k], bb = v[s + k + h];
                    v[s + k]     = a + bb;
                    v[s + k + h] = a - bb;
                }

        float* o1 = out1 + base + j * DIM_C + c;
#pragma unroll
        for (int i = 0; i < 64; i++) {
            sm[i * ROWF + col]      = v[i];
            o1[(size_t)i * 8192]    = v[i];
        }
    }
    __syncthreads();

    // ---------- phase B: FWHT over j; write out2 from regs ----------
    {
        const int i = t >> 2;
        const int c = t & 3;
        const int rowoff = i * ROWF + c;
#pragma unroll
        for (int j = 0; j < 64; j++) v[j] = sm[rowoff + j * 4];

#pragma unroll
        for (int h = 1; h < 64; h <<= 1)
#pragma unroll
            for (int s = 0; s < 64; s += 2 * h)
#pragma unroll
                for (int k = 0; k < h; k++) {
                    float a = v[s + k], bb = v[s + k + h];
                    v[s + k]     = a + bb;
                    v[s + k + h] = a - bb;
                }

        float* o2 = out2 + base + (size_t)i * 8192 + c;
#pragma unroll
        for (int j = 0; j < 64; j++)
            o2[j * DIM_C] = v[j];
    }
}

extern "C" void kernel_launch(void* const* d_in, const int* in_sizes, int n_in,
                              void* d_out, int out_size)
{
    const float* x = (const float*)d_in[0];
    float* out1 = (float*)d_out;
    float* out2 = out1 + (size_t)64 * 64 * 64 * 128;

    cudaFuncSetAttribute(wht2_fused,
                         cudaFuncAttributeMaxDynamicSharedMemorySize, SMEM_BYTES);

    wht2_fused<<<64 * 32, 256, SMEM_BYTES>>>(x, out1, out2);
}

// round 4
// speedup vs baseline: 2.7761x; 2.7761x over previous
#include <cuda_runtime.h>

// x[64, 64, 64, 128] fp32.
//   out1 = FWHT along axis 1 (i, len 64)  : element stride 64*128 = 8192
//   out2 = FWHT along axis 2 (j, len 64) of out1 : element stride 128
// d_out = [out1 | out2], 2 * 64^3 * 128 floats.
//
// Two streaming kernels, one thread per scalar column along the transform
// axis; all gmem accesses warp-contiguous; butterfly in registers.
// L2 exploitation: out1 (128 MB) nearly fits in L2 (126 MB). Kernel 1 reads
// x with evict-first (__ldcs) so out1 writes stay resident; kernel 2 walks
// the data in REVERSE block order (freshest-written out1 first) and writes
// out2 with evict-first (__stcs) to avoid evicting the out1 lines it still
// needs.

#define THREADS 256
#define NCOLS (64u * 64u * 64u * 128u / 64u)   // 2^19 columns per kernel
#define GRID   (NCOLS / THREADS)               // 2048

template <int STRIDE, bool REVERSE>
__global__ __launch_bounds__(THREADS)
void fwht_axis_kernel(const float* __restrict__ in, float* __restrict__ out)
{
    const unsigned blk = REVERSE ? (GRID - 1u - blockIdx.x) : blockIdx.x;
    const unsigned g   = blk * THREADS + threadIdx.x;        // 0 .. 2^19-1
    const size_t base  = (size_t)(g / STRIDE) * (64u * STRIDE) + (g % STRIDE);

    float v[64];
#pragma unroll
    for (int k = 0; k < 64; k++)
        v[k] = __ldcs(in + base + (size_t)k * STRIDE);       // use-once read

#pragma unroll
    for (int h = 1; h < 64; h <<= 1) {
#pragma unroll
        for (int s = 0; s < 64; s += 2 * h) {
#pragma unroll
            for (int k = 0; k < h; k++) {
                float a = v[s + k];
                float b = v[s + k + h];
                v[s + k]     = a + b;
                v[s + k + h] = a - b;
            }
        }
    }

    if (REVERSE) {
        // out2: use-once write, evict-first to preserve out1 in L2
#pragma unroll
        for (int k = 0; k < 64; k++)
            __stcs(out + base + (size_t)k * STRIDE, v[k]);
    } else {
        // out1: default policy — we WANT these lines resident for kernel 2
#pragma unroll
        for (int k = 0; k < 64; k++)
            out[base + (size_t)k * STRIDE] = v[k];
    }
}

extern "C" void kernel_launch(void* const* d_in, const int* in_sizes, int n_in,
                              void* d_out, int out_size)
{
    const float* x = (const float*)d_in[0];
    float* out1 = (float*)d_out;
    float* out2 = out1 + (size_t)64 * 64 * 64 * 128;

    // axis 1: stride J*C = 8192, forward order
    fwht_axis_kernel<8192, false><<<GRID, THREADS>>>(x, out1);
    // axis 2: stride C = 128, reverse order (consume freshest out1 first)
    fwht_axis_kernel<128, true><<<GRID, THREADS>>>(out1, out2);
}